// round 2
// baseline (speedup 1.0000x reference)
#include <cuda_runtime.h>
#include <cuda_fp16.h>
#include <stdint.h>

// Problem: B=128, H=64, D=64.  8192 (b,h) tiles of 64x64.
// Outputs concatenated: memory_output[33554432] | scores[33554432] |
//                       new_memory_key[4096] | new_memory_norm[64]

#define GRED 512  // stats partial blocks (16 tiles each)

// ---------------- device scratch (no runtime allocation allowed) ------------
__device__ float  g_pk[GRED * 4096];
__device__ float  g_pv[GRED * 4096];
__device__ float  g_pb[GRED * 64];
__device__ float  g_mvmean[4096];
__device__ float  g_mb[64];
__device__ float  g_prenorm[64];
__device__ float  g_inv[64];
__device__ __half g_MKT[64 * 4096];  // per-h MK^T  (row m, col n)  fp16
__device__ __half g_MVh[64 * 4096];  // per-h MV hi (row n, col m)  fp16
__device__ __half g_MVl[64 * 4096];  // per-h MV lo residual        fp16

// ---------------- PTX helpers ----------------
static __device__ __forceinline__ uint32_t smem_u32(const void* p) {
    return (uint32_t)__cvta_generic_to_shared(p);
}
static __device__ __forceinline__ void ldsm_x4(uint32_t* r, uint32_t a) {
    asm volatile("ldmatrix.sync.aligned.m8n8.x4.shared.b16 {%0,%1,%2,%3}, [%4];"
                 : "=r"(r[0]), "=r"(r[1]), "=r"(r[2]), "=r"(r[3]) : "r"(a));
}
static __device__ __forceinline__ void ldsm_x4_t(uint32_t* r, uint32_t a) {
    asm volatile("ldmatrix.sync.aligned.m8n8.x4.trans.shared.b16 {%0,%1,%2,%3}, [%4];"
                 : "=r"(r[0]), "=r"(r[1]), "=r"(r[2]), "=r"(r[3]) : "r"(a));
}
static __device__ __forceinline__ void mma16816(float* c, const uint32_t* a,
                                                uint32_t b0, uint32_t b1) {
    asm volatile("mma.sync.aligned.m16n8k16.row.col.f32.f16.f16.f32 "
                 "{%0,%1,%2,%3}, {%4,%5,%6,%7}, {%8,%9}, {%0,%1,%2,%3};"
                 : "+f"(c[0]), "+f"(c[1]), "+f"(c[2]), "+f"(c[3])
                 : "r"(a[0]), "r"(a[1]), "r"(a[2]), "r"(a[3]), "r"(b0), "r"(b1));
}
static __device__ __forceinline__ float h16(float x) {
    return __half2float(__float2half_rn(x));
}

// ---------------- Kernel 1: streaming key/value statistics ------------------
// 256 threads, 16 tiles per block. Thread t owns flat elems 1024*i+4t (i<4):
// rows n = 16i + (t>>4), cols d = 4*(t&15)..+3.
__global__ void __launch_bounds__(256) stats_kernel(const float* __restrict__ key,
                                                    const float* __restrict__ value) {
    __shared__ float red[16 * 68];     // [R][d] column partials (68: float4-aligned pad)
    __shared__ float ks[64];           // per-tile sum_n fp16(key[n,d])
    __shared__ float pbred[64 * 17];   // [m][c] binding partials
    const int t = threadIdx.x;
    const int R = t >> 4;
    const int c = t & 15;
    const int d0 = c << 2;
    float pk[16], pv[16];
#pragma unroll
    for (int i = 0; i < 16; i++) { pk[i] = 0.f; pv[i] = 0.f; }
    float pb_acc = 0.f;
    const int tile0 = blockIdx.x * 16;

    for (int tt = 0; tt < 16; tt++) {
        const float4* kb = (const float4*)(key + ((size_t)(tile0 + tt) << 12));
        const float4* vb = (const float4*)(value + ((size_t)(tile0 + tt) << 12));
        float4 kq[4];
#pragma unroll
        for (int i = 0; i < 4; i++) kq[i] = kb[256 * i + t];
        float s0 = 0.f, s1 = 0.f, s2 = 0.f, s3 = 0.f;
#pragma unroll
        for (int i = 0; i < 4; i++) {
            pk[4 * i + 0] += kq[i].x; pk[4 * i + 1] += kq[i].y;
            pk[4 * i + 2] += kq[i].z; pk[4 * i + 3] += kq[i].w;
            s0 += h16(kq[i].x); s1 += h16(kq[i].y);
            s2 += h16(kq[i].z); s3 += h16(kq[i].w);
        }
        *(float4*)&red[R * 68 + d0] = make_float4(s0, s1, s2, s3);
        __syncthreads();
        if (t < 64) {
            float acc = 0.f;
#pragma unroll
            for (int r = 0; r < 16; r++) acc += red[r * 68 + t];
            ks[t] = acc;
        }
        __syncthreads();
        const float4 kv = *(const float4*)&ks[d0];
        float4 vq[4];
#pragma unroll
        for (int i = 0; i < 4; i++) vq[i] = vb[256 * i + t];
#pragma unroll
        for (int i = 0; i < 4; i++) {
            pv[4 * i + 0] += vq[i].x; pv[4 * i + 1] += vq[i].y;
            pv[4 * i + 2] += vq[i].z; pv[4 * i + 3] += vq[i].w;
            float p = h16(vq[i].x) * kv.x + h16(vq[i].y) * kv.y
                    + h16(vq[i].z) * kv.z + h16(vq[i].w) * kv.w;
            pbred[(16 * i + R) * 17 + c] = p;
        }
        __syncthreads();
        if (t < 64) {
            float acc = 0.f;
#pragma unroll
            for (int cc = 0; cc < 16; cc++) acc += pbred[t * 17 + cc];
            pb_acc += acc;
        }
        __syncthreads();
    }
    float4* pkd = (float4*)(g_pk + (size_t)blockIdx.x * 4096);
    float4* pvd = (float4*)(g_pv + (size_t)blockIdx.x * 4096);
#pragma unroll
    for (int i = 0; i < 4; i++) {
        pkd[256 * i + t] = make_float4(pk[4 * i], pk[4 * i + 1], pk[4 * i + 2], pk[4 * i + 3]);
        pvd[256 * i + t] = make_float4(pv[4 * i], pv[4 * i + 1], pv[4 * i + 2], pv[4 * i + 3]);
    }
    if (t < 64) g_pb[blockIdx.x * 64 + t] = pb_acc;
}

// ---------------- Kernel 2: prep fp16 operand matrices ----------------------
__global__ void prep_kernel(const float* __restrict__ mk, const float* __restrict__ mv,
                            const float* __restrict__ norm) {
    const int h = blockIdx.x, t = threadIdx.x;
    const float* mkh = mk + h * 4096;
    const float* mvh = mv + h * 4096;
    for (int idx = t; idx < 4096; idx += 256) {
        int n = idx >> 6, m = idx & 63;
        g_MKT[h * 4096 + m * 64 + n] = __float2half_rn(mkh[idx]);  // MK^T
        float v = mvh[idx];
        __half hi = __float2half_rn(v);
        g_MVh[h * 4096 + idx] = hi;
        g_MVl[h * 4096 + idx] = __float2half_rn(v - __half2float(hi));
    }
    if (h == 0 && t < 64) g_inv[t] = 1.0f / (norm[t] + 1e-6f);
}

// ---------------- Kernel 3: fused retrieve (scores + memory_output) ---------
// grid (32 b-chunks, 64 h), 128 threads. Per CTA: hoisted MK^T / MV_hi / MV_lo
// A-fragments in registers, 4 b-tiles. Smem stride 72 halves (conflict-free).
__global__ void __launch_bounds__(128) retrieve_kernel(const float* __restrict__ query,
                                                       float* __restrict__ outO,
                                                       float* __restrict__ outS) {
    __shared__ __align__(16) __half sm[5 * 64 * 72];
    __shared__ float sInv[64];
    __half* sMKT = sm;
    __half* sMVh = sm + 4608;
    __half* sMVl = sm + 9216;
    __half* sQ   = sm + 13824;
    __half* sS   = sm + 18432;
    const int t = threadIdx.x;
    const int h = blockIdx.y;
    const int w = t >> 5, l = t & 31;

    {   // stage per-h operand matrices + inv
        const uint32_t* s0 = (const uint32_t*)(g_MKT + h * 4096);
        const uint32_t* s1 = (const uint32_t*)(g_MVh + h * 4096);
        const uint32_t* s2 = (const uint32_t*)(g_MVl + h * 4096);
        for (int w32 = t; w32 < 2048; w32 += 128) {
            int row = w32 >> 5, c2 = (w32 & 31) * 2;
            int dst = row * 72 + c2;
            *(uint32_t*)&sMKT[dst] = s0[w32];
            *(uint32_t*)&sMVh[dst] = s1[w32];
            *(uint32_t*)&sMVl[dst] = s2[w32];
        }
        if (t < 64) sInv[t] = g_inv[t];
    }
    __syncthreads();

    // hoist A fragments (rows 16w..16w+15, four k16 steps)
    uint32_t a1[4][4], a2h[4][4], a2l[4][4];
    {
        const uint32_t rb = (uint32_t)((16 * w + (l & 15)) * 72 + (l >> 4) * 8);
#pragma unroll
        for (int k = 0; k < 4; k++) {
            ldsm_x4(a1[k],  smem_u32(&sMKT[rb + 16 * k]));
            ldsm_x4(a2h[k], smem_u32(&sMVh[rb + 16 * k]));
            ldsm_x4(a2l[k], smem_u32(&sMVl[rb + 16 * k]));
        }
    }
    const uint32_t rbB = (uint32_t)((l & 15) * 72 + (l >> 4) * 8);
    const int r0 = 16 * w + (l >> 2);
    const int cbase = 2 * (l & 3);

    for (int i = 0; i < 4; i++) {
        const int b = blockIdx.x * 4 + i;
        const size_t tile = ((size_t)(b * 64 + h)) << 12;
        // load Q -> fp16 smem
        const float4* qp = (const float4*)(query + tile);
#pragma unroll
        for (int j = 0; j < 8; j++) {
            int e4 = j * 128 + t;
            float4 v = qp[e4];
            int row = e4 >> 4, c4 = (e4 & 15) * 4;
            __half2* dq = (__half2*)&sQ[row * 72 + c4];
            dq[0] = __floats2half2_rn(v.x, v.y);
            dq[1] = __floats2half2_rn(v.z, v.w);
        }
        __syncthreads();

        // GEMM1: S[m,d] = sum_n MK^T[m,n] * Q[n,d]   (f16 x f16 -> f32)
        float c[8][4];
#pragma unroll
        for (int j = 0; j < 8; j++)
#pragma unroll
            for (int q = 0; q < 4; q++) c[j][q] = 0.f;
#pragma unroll
        for (int k = 0; k < 4; k++)
#pragma unroll
            for (int j = 0; j < 4; j++) {
                uint32_t br[4];
                ldsm_x4_t(br, smem_u32(&sQ[16 * k * 72 + rbB + 16 * j]));
                mma16816(c[2 * j],     a1[k], br[0], br[1]);
                mma16816(c[2 * j + 1], a1[k], br[2], br[3]);
            }

        // round to fp16 (reference f16 einsum output), store S16, emit scores
        float* scoresT = outS + tile;
#pragma unroll
        for (int j = 0; j < 8; j++) {
            int col = 8 * j + cbase;
            __half2 h0 = __floats2half2_rn(c[j][0], c[j][1]);
            __half2 h1 = __floats2half2_rn(c[j][2], c[j][3]);
            *(__half2*)&sS[r0 * 72 + col]       = h0;
            *(__half2*)&sS[(r0 + 8) * 72 + col] = h1;
            float2 iv = *(float2*)&sInv[col];
            *(float2*)&scoresT[r0 * 64 + col] =
                make_float2(__low2float(h0) * iv.x, __high2float(h0) * iv.y);
            *(float2*)&scoresT[(r0 + 8) * 64 + col] =
                make_float2(__low2float(h1) * iv.x, __high2float(h1) * iv.y);
        }
        __syncthreads();

        // GEMM2: out[n,d] = inv[d] * sum_m (MVhi+MVlo)[n,m] * S16[m,d]
        float o[8][4];
#pragma unroll
        for (int j = 0; j < 8; j++)
#pragma unroll
            for (int q = 0; q < 4; q++) o[j][q] = 0.f;
#pragma unroll
        for (int k = 0; k < 4; k++)
#pragma unroll
            for (int j = 0; j < 4; j++) {
                uint32_t br[4];
                ldsm_x4_t(br, smem_u32(&sS[16 * k * 72 + rbB + 16 * j]));
                mma16816(o[2 * j],     a2h[k], br[0], br[1]);
                mma16816(o[2 * j + 1], a2h[k], br[2], br[3]);
                mma16816(o[2 * j],     a2l[k], br[0], br[1]);
                mma16816(o[2 * j + 1], a2l[k], br[2], br[3]);
            }
        float* outT = outO + tile;
#pragma unroll
        for (int j = 0; j < 8; j++) {
            int col = 8 * j + cbase;
            float2 iv = *(float2*)&sInv[col];
            *(float2*)&outT[r0 * 64 + col] =
                make_float2(o[j][0] * iv.x, o[j][1] * iv.y);
            *(float2*)&outT[(r0 + 8) * 64 + col] =
                make_float2(o[j][2] * iv.x, o[j][3] * iv.y);
        }
        // no trailing sync needed: next-iter S-store is fenced by the post-Q sync
    }
}

// ---------------- Kernel 4: reduce stats partials ---------------------------
__global__ void reduce_kernel(const float* __restrict__ memory_norm) {
    const int n = blockIdx.x;
    const int d = threadIdx.x & 63;
    const int q = threadIdx.x >> 6;
    float spk = 0.f, spv = 0.f, spb = 0.f;
    for (int g = q; g < GRED; g += 4) {
        spk += g_pk[(size_t)g * 4096 + n * 64 + d];
        spv += g_pv[(size_t)g * 4096 + n * 64 + d];
    }
    if (n == 0)
        for (int g = q; g < GRED; g += 4) spb += g_pb[g * 64 + d];
    __shared__ float rk[4][64], rv[4][64], rb[4][64], kk[64];
    rk[q][d] = spk; rv[q][d] = spv; rb[q][d] = spb;
    __syncthreads();
    if (q == 0) {
        float k = (rk[0][d] + rk[1][d] + rk[2][d] + rk[3][d]) * (1.f / 8192.f);
        float v = (rv[0][d] + rv[1][d] + rv[2][d] + rv[3][d]) * (1.f / 8192.f);
        g_mvmean[n * 64 + d] = v;
        if (n == 0)
            g_mb[d] = (rb[0][d] + rb[1][d] + rb[2][d] + rb[3][d]) * (1.f / 524288.f);
        kk[d] = k * k;
    }
    __syncthreads();
    if (threadIdx.x == 0) {
        float s = 0.f;
#pragma unroll
        for (int i = 0; i < 64; i++) s += kk[i];
        g_prenorm[n] = memory_norm[n] + sqrtf(s);
    }
}

// ---------------- Kernel 5: finalize new_memory_key / new_memory_norm -------
__global__ void finalize_kernel(const float* __restrict__ cr,
                                float* __restrict__ out_mk,
                                float* __restrict__ out_norm) {
    __shared__ float pn[64];
    __shared__ float meanv;
    const int t = threadIdx.x;  // 64 threads
    pn[t] = g_prenorm[t];
    __syncthreads();
    if (t == 0) {
        float s = 0.f;
#pragma unroll
        for (int i = 0; i < 64; i++) s += pn[i];
        meanv = s * (1.f / 64.f);
    }
    __syncthreads();
    const float f = (meanv > 0.9f) ? cr[t] : 1.0f;
    out_norm[t] = pn[t] * f;
    const float mb = g_mb[t] * f;
    for (int d = 0; d < 64; d++) out_mk[t * 64 + d] = mb * g_mvmean[t * 64 + d];
}

// ---------------- launcher ----------------
extern "C" void kernel_launch(void* const* d_in, const int* in_sizes, int n_in,
                              void* d_out, int out_size) {
    const float* query = (const float*)d_in[0];
    const float* key   = (const float*)d_in[1];
    const float* value = (const float*)d_in[2];
    const float* mk    = (const float*)d_in[3];
    const float* mnorm = (const float*)d_in[4];
    const float* mv    = (const float*)d_in[5];
    const float* cr    = (const float*)d_in[6];
    float* out   = (float*)d_out;
    float* outO  = out;                 // memory_output [128,64,64,64]
    float* outS  = out + 33554432;      // scores        [128,64,64,64]
    float* outMK = out + 67108864;      // new_memory_key  [64,64]
    float* outN  = out + 67112960;      // new_memory_norm [64]

    stats_kernel<<<GRED, 256>>>(key, value);
    prep_kernel<<<64, 256>>>(mk, mv, mnorm);
    retrieve_kernel<<<dim3(32, 64), 128>>>(query, outO, outS);
    reduce_kernel<<<64, 256>>>(mnorm);
    finalize_kernel<<<1, 64>>>(cr, outMK, outN);
}

// round 4
// speedup vs baseline: 1.0091x; 1.0091x over previous
#include <cuda_runtime.h>
#include <cuda_fp16.h>
#include <stdint.h>

// Problem: B=128, H=64, D=64.  8192 (b,h) tiles of 64x64.
// Outputs concatenated: memory_output[33554432] | scores[33554432] |
//                       new_memory_key[4096] | new_memory_norm[64]

#define GRED 512  // stats partial blocks (16 tiles each)

// ---------------- device scratch (no runtime allocation allowed) ------------
__device__ float  g_pk[GRED * 4096];
__device__ float  g_pv[GRED * 4096];
__device__ float  g_pb[GRED * 64];
__device__ float  g_mvmean[4096];
__device__ float  g_mb[64];
__device__ float  g_prenorm[64];
__device__ float  g_inv[64];
__device__ __half g_MKT[64 * 4096];  // per-h MK^T  (row m, col n)  fp16
__device__ __half g_MVh[64 * 4096];  // per-h MV hi (row n, col m)  fp16
__device__ __half g_MVl[64 * 4096];  // per-h MV lo residual        fp16

// ---------------- PTX helpers ----------------
static __device__ __forceinline__ uint32_t smem_u32(const void* p) {
    return (uint32_t)__cvta_generic_to_shared(p);
}
static __device__ __forceinline__ void ldsm_x4(uint32_t* r, uint32_t a) {
    asm volatile("ldmatrix.sync.aligned.m8n8.x4.shared.b16 {%0,%1,%2,%3}, [%4];"
                 : "=r"(r[0]), "=r"(r[1]), "=r"(r[2]), "=r"(r[3]) : "r"(a));
}
static __device__ __forceinline__ void ldsm_x4_t(uint32_t* r, uint32_t a) {
    asm volatile("ldmatrix.sync.aligned.m8n8.x4.trans.shared.b16 {%0,%1,%2,%3}, [%4];"
                 : "=r"(r[0]), "=r"(r[1]), "=r"(r[2]), "=r"(r[3]) : "r"(a));
}
static __device__ __forceinline__ void mma16816(float* c, const uint32_t* a,
                                                uint32_t b0, uint32_t b1) {
    asm volatile("mma.sync.aligned.m16n8k16.row.col.f32.f16.f16.f32 "
                 "{%0,%1,%2,%3}, {%4,%5,%6,%7}, {%8,%9}, {%0,%1,%2,%3};"
                 : "+f"(c[0]), "+f"(c[1]), "+f"(c[2]), "+f"(c[3])
                 : "r"(a[0]), "r"(a[1]), "r"(a[2]), "r"(a[3]), "r"(b0), "r"(b1));
}
static __device__ __forceinline__ float h16(float x) {
    return __half2float(__float2half_rn(x));
}

// ---------------- Kernel 1: streaming key/value statistics ------------------
// 256 threads, 16 tiles per block. Thread t owns flat elems 1024*i+4t (i<4):
// rows n = 16i + (t>>4), cols d = 4*(t&15)..+3.
__global__ void __launch_bounds__(256) stats_kernel(const float* __restrict__ key,
                                                    const float* __restrict__ value) {
    __shared__ float red[16 * 68];     // [R][d] column partials (68: float4-aligned pad)
    __shared__ float ks[64];           // per-tile sum_n fp16(key[n,d])
    __shared__ float pbred[64 * 17];   // [m][c] binding partials
    const int t = threadIdx.x;
    const int R = t >> 4;
    const int c = t & 15;
    const int d0 = c << 2;
    float pk[16], pv[16];
#pragma unroll
    for (int i = 0; i < 16; i++) { pk[i] = 0.f; pv[i] = 0.f; }
    float pb_acc = 0.f;
    const int tile0 = blockIdx.x * 16;

    for (int tt = 0; tt < 16; tt++) {
        const float4* kb = (const float4*)(key + ((size_t)(tile0 + tt) << 12));
        const float4* vb = (const float4*)(value + ((size_t)(tile0 + tt) << 12));
        float4 kq[4];
#pragma unroll
        for (int i = 0; i < 4; i++) kq[i] = kb[256 * i + t];
        float s0 = 0.f, s1 = 0.f, s2 = 0.f, s3 = 0.f;
#pragma unroll
        for (int i = 0; i < 4; i++) {
            pk[4 * i + 0] += kq[i].x; pk[4 * i + 1] += kq[i].y;
            pk[4 * i + 2] += kq[i].z; pk[4 * i + 3] += kq[i].w;
            s0 += h16(kq[i].x); s1 += h16(kq[i].y);
            s2 += h16(kq[i].z); s3 += h16(kq[i].w);
        }
        *(float4*)&red[R * 68 + d0] = make_float4(s0, s1, s2, s3);
        __syncthreads();
        if (t < 64) {
            float acc = 0.f;
#pragma unroll
            for (int r = 0; r < 16; r++) acc += red[r * 68 + t];
            ks[t] = acc;
        }
        __syncthreads();
        const float4 kv = *(const float4*)&ks[d0];
        float4 vq[4];
#pragma unroll
        for (int i = 0; i < 4; i++) vq[i] = vb[256 * i + t];
#pragma unroll
        for (int i = 0; i < 4; i++) {
            pv[4 * i + 0] += vq[i].x; pv[4 * i + 1] += vq[i].y;
            pv[4 * i + 2] += vq[i].z; pv[4 * i + 3] += vq[i].w;
            float p = h16(vq[i].x) * kv.x + h16(vq[i].y) * kv.y
                    + h16(vq[i].z) * kv.z + h16(vq[i].w) * kv.w;
            pbred[(16 * i + R) * 17 + c] = p;
        }
        __syncthreads();
        if (t < 64) {
            float acc = 0.f;
#pragma unroll
            for (int cc = 0; cc < 16; cc++) acc += pbred[t * 17 + cc];
            pb_acc += acc;
        }
        __syncthreads();
    }
    float4* pkd = (float4*)(g_pk + (size_t)blockIdx.x * 4096);
    float4* pvd = (float4*)(g_pv + (size_t)blockIdx.x * 4096);
#pragma unroll
    for (int i = 0; i < 4; i++) {
        pkd[256 * i + t] = make_float4(pk[4 * i], pk[4 * i + 1], pk[4 * i + 2], pk[4 * i + 3]);
        pvd[256 * i + t] = make_float4(pv[4 * i], pv[4 * i + 1], pv[4 * i + 2], pv[4 * i + 3]);
    }
    if (t < 64) g_pb[blockIdx.x * 64 + t] = pb_acc;
}

// ---------------- Kernel 2: prep fp16 operand matrices ----------------------
__global__ void prep_kernel(const float* __restrict__ mk, const float* __restrict__ mv,
                            const float* __restrict__ norm) {
    const int h = blockIdx.x, t = threadIdx.x;
    const float* mkh = mk + h * 4096;
    const float* mvh = mv + h * 4096;
    for (int idx = t; idx < 4096; idx += 256) {
        int n = idx >> 6, m = idx & 63;
        g_MKT[h * 4096 + m * 64 + n] = __float2half_rn(mkh[idx]);  // MK^T
        float v = mvh[idx];
        __half hi = __float2half_rn(v);
        g_MVh[h * 4096 + idx] = hi;
        g_MVl[h * 4096 + idx] = __float2half_rn(v - __half2float(hi));
    }
    if (h == 0 && t < 64) g_inv[t] = 1.0f / (norm[t] + 1e-6f);
}

// ---------------- Kernel 3: fused retrieve (scores + memory_output) ---------
// grid (32 b-chunks, 64 h), 128 threads. Per CTA: hoisted MK^T / MV_hi / MV_lo
// A-fragments in registers, 4 b-tiles. Smem stride 72 halves (conflict-free).
__global__ void __launch_bounds__(128) retrieve_kernel(const float* __restrict__ query,
                                                       float* __restrict__ outO,
                                                       float* __restrict__ outS) {
    __shared__ __align__(16) __half sm[5 * 64 * 72];
    __shared__ float sInv[64];
    __half* sMKT = sm;
    __half* sMVh = sm + 4608;
    __half* sMVl = sm + 9216;
    __half* sQ   = sm + 13824;
    __half* sS   = sm + 18432;
    const int t = threadIdx.x;
    const int h = blockIdx.y;
    const int w = t >> 5, l = t & 31;

    {   // stage per-h operand matrices + inv
        const uint32_t* s0 = (const uint32_t*)(g_MKT + h * 4096);
        const uint32_t* s1 = (const uint32_t*)(g_MVh + h * 4096);
        const uint32_t* s2 = (const uint32_t*)(g_MVl + h * 4096);
        for (int w32 = t; w32 < 2048; w32 += 128) {
            int row = w32 >> 5, c2 = (w32 & 31) * 2;
            int dst = row * 72 + c2;
            *(uint32_t*)&sMKT[dst] = s0[w32];
            *(uint32_t*)&sMVh[dst] = s1[w32];
            *(uint32_t*)&sMVl[dst] = s2[w32];
        }
        if (t < 64) sInv[t] = g_inv[t];
    }
    __syncthreads();

    // hoist A fragments (rows 16w..16w+15, four k16 steps)
    uint32_t a1[4][4], a2h[4][4], a2l[4][4];
    {
        const uint32_t rb = (uint32_t)((16 * w + (l & 15)) * 72 + (l >> 4) * 8);
#pragma unroll
        for (int k = 0; k < 4; k++) {
            ldsm_x4(a1[k],  smem_u32(&sMKT[rb + 16 * k]));
            ldsm_x4(a2h[k], smem_u32(&sMVh[rb + 16 * k]));
            ldsm_x4(a2l[k], smem_u32(&sMVl[rb + 16 * k]));
        }
    }
    const uint32_t rbB = (uint32_t)((l & 15) * 72 + (l >> 4) * 8);
    const int r0 = 16 * w + (l >> 2);
    const int cbase = 2 * (l & 3);

    for (int i = 0; i < 4; i++) {
        const int b = blockIdx.x * 4 + i;
        const size_t tile = ((size_t)(b * 64 + h)) << 12;
        // load Q -> fp16 smem
        const float4* qp = (const float4*)(query + tile);
#pragma unroll
        for (int j = 0; j < 8; j++) {
            int e4 = j * 128 + t;
            float4 v = qp[e4];
            int row = e4 >> 4, c4 = (e4 & 15) * 4;
            __half2* dq = (__half2*)&sQ[row * 72 + c4];
            dq[0] = __floats2half2_rn(v.x, v.y);
            dq[1] = __floats2half2_rn(v.z, v.w);
        }
        __syncthreads();

        // GEMM1: S[m,d] = sum_n MK^T[m,n] * Q[n,d]   (f16 x f16 -> f32)
        float c[8][4];
#pragma unroll
        for (int j = 0; j < 8; j++)
#pragma unroll
            for (int q = 0; q < 4; q++) c[j][q] = 0.f;
#pragma unroll
        for (int k = 0; k < 4; k++)
#pragma unroll
            for (int j = 0; j < 4; j++) {
                uint32_t br[4];
                ldsm_x4_t(br, smem_u32(&sQ[16 * k * 72 + rbB + 16 * j]));
                mma16816(c[2 * j],     a1[k], br[0], br[1]);
                mma16816(c[2 * j + 1], a1[k], br[2], br[3]);
            }

        // round to fp16 (reference f16 einsum output), store S16, emit scores
        float* scoresT = outS + tile;
#pragma unroll
        for (int j = 0; j < 8; j++) {
            int col = 8 * j + cbase;
            __half2 h0 = __floats2half2_rn(c[j][0], c[j][1]);
            __half2 h1 = __floats2half2_rn(c[j][2], c[j][3]);
            *(__half2*)&sS[r0 * 72 + col]       = h0;
            *(__half2*)&sS[(r0 + 8) * 72 + col] = h1;
            float2 iv = *(float2*)&sInv[col];
            *(float2*)&scoresT[r0 * 64 + col] =
                make_float2(__low2float(h0) * iv.x, __high2float(h0) * iv.y);
            *(float2*)&scoresT[(r0 + 8) * 64 + col] =
                make_float2(__low2float(h1) * iv.x, __high2float(h1) * iv.y);
        }
        __syncthreads();

        // GEMM2: out[n,d] = inv[d] * sum_m (MVhi+MVlo)[n,m] * S16[m,d]
        float o[8][4];
#pragma unroll
        for (int j = 0; j < 8; j++)
#pragma unroll
            for (int q = 0; q < 4; q++) o[j][q] = 0.f;
#pragma unroll
        for (int k = 0; k < 4; k++)
#pragma unroll
            for (int j = 0; j < 4; j++) {
                uint32_t br[4];
                ldsm_x4_t(br, smem_u32(&sS[16 * k * 72 + rbB + 16 * j]));
                mma16816(o[2 * j],     a2h[k], br[0], br[1]);
                mma16816(o[2 * j + 1], a2h[k], br[2], br[3]);
                mma16816(o[2 * j],     a2l[k], br[0], br[1]);
                mma16816(o[2 * j + 1], a2l[k], br[2], br[3]);
            }
        float* outT = outO + tile;
#pragma unroll
        for (int j = 0; j < 8; j++) {
            int col = 8 * j + cbase;
            float2 iv = *(float2*)&sInv[col];
            *(float2*)&outT[r0 * 64 + col] =
                make_float2(o[j][0] * iv.x, o[j][1] * iv.y);
            *(float2*)&outT[(r0 + 8) * 64 + col] =
                make_float2(o[j][2] * iv.x, o[j][3] * iv.y);
        }
        // no trailing sync needed: next-iter S-store is fenced by the post-Q sync
    }
}

// ---------------- Kernel 4: reduce stats partials ---------------------------
__global__ void reduce_kernel(const float* __restrict__ memory_norm) {
    const int n = blockIdx.x;
    const int d = threadIdx.x & 63;
    const int q = threadIdx.x >> 6;
    float spk = 0.f, spv = 0.f, spb = 0.f;
    for (int g = q; g < GRED; g += 4) {
        spk += g_pk[(size_t)g * 4096 + n * 64 + d];
        spv += g_pv[(size_t)g * 4096 + n * 64 + d];
    }
    if (n == 0)
        for (int g = q; g < GRED; g += 4) spb += g_pb[g * 64 + d];
    __shared__ float rk[4][64], rv[4][64], rb[4][64], kk[64];
    rk[q][d] = spk; rv[q][d] = spv; rb[q][d] = spb;
    __syncthreads();
    if (q == 0) {
        float k = (rk[0][d] + rk[1][d] + rk[2][d] + rk[3][d]) * (1.f / 8192.f);
        float v = (rv[0][d] + rv[1][d] + rv[2][d] + rv[3][d]) * (1.f / 8192.f);
        g_mvmean[n * 64 + d] = v;
        if (n == 0)
            g_mb[d] = (rb[0][d] + rb[1][d] + rb[2][d] + rb[3][d]) * (1.f / 524288.f);
        kk[d] = k * k;
    }
    __syncthreads();
    if (threadIdx.x == 0) {
        float s = 0.f;
#pragma unroll
        for (int i = 0; i < 64; i++) s += kk[i];
        g_prenorm[n] = memory_norm[n] + sqrtf(s);
    }
}

// ---------------- Kernel 5: finalize new_memory_key / new_memory_norm -------
__global__ void finalize_kernel(const float* __restrict__ cr,
                                float* __restrict__ out_mk,
                                float* __restrict__ out_norm) {
    __shared__ float pn[64];
    __shared__ float meanv;
    const int t = threadIdx.x;  // 64 threads
    pn[t] = g_prenorm[t];
    __syncthreads();
    if (t == 0) {
        float s = 0.f;
#pragma unroll
        for (int i = 0; i < 64; i++) s += pn[i];
        meanv = s * (1.f / 64.f);
    }
    __syncthreads();
    const float f = (meanv > 0.9f) ? cr[t] : 1.0f;
    out_norm[t] = pn[t] * f;
    const float mb = g_mb[t] * f;
    for (int d = 0; d < 64; d++) out_mk[t * 64 + d] = mb * g_mvmean[t * 64 + d];
}

// ---------------- launcher ----------------
extern "C" void kernel_launch(void* const* d_in, const int* in_sizes, int n_in,
                              void* d_out, int out_size) {
    const float* query = (const float*)d_in[0];
    const float* key   = (const float*)d_in[1];
    const float* value = (const float*)d_in[2];
    const float* mk    = (const float*)d_in[3];
    const float* mnorm = (const float*)d_in[4];
    const float* mv    = (const float*)d_in[5];
    const float* cr    = (const float*)d_in[6];
    float* out   = (float*)d_out;
    float* outO  = out;                 // memory_output [128,64,64,64]
    float* outS  = out + 33554432;      // scores        [128,64,64,64]
    float* outMK = out + 67108864;      // new_memory_key  [64,64]
    float* outN  = out + 67112960;      // new_memory_norm [64]

    stats_kernel<<<GRED, 256>>>(key, value);
    prep_kernel<<<64, 256>>>(mk, mv, mnorm);
    retrieve_kernel<<<dim3(32, 64), 128>>>(query, outO, outS);
    reduce_kernel<<<64, 256>>>(mnorm);
    finalize_kernel<<<1, 64>>>(cr, outMK, outN);
}